// round 4
// baseline (speedup 1.0000x reference)
#include <cuda_runtime.h>
#include <cstdint>

namespace {

constexpr int T_SEQ  = 4096;
constexpr int D_HEAD = 128;
constexpr int BM = 64;
constexpr int BN = 64;
constexpr int SSTRIDE  = 132;  // Q/K tiles: pad 4 -> ldmatrix conflict-free
constexpr int VSTRIDE  = 136;  // V tile: pad 8 -> conflict-free scalar B-fragment LDS
constexpr int SMEM_BYTES = (2 * BM * SSTRIDE + BN * VSTRIDE) * 4;  // 102400 B -> 2 CTAs/SM

__device__ __forceinline__ uint32_t f2tf32(float x) {
  uint32_t u;
  asm("cvt.rna.tf32.f32 %0, %1;" : "=r"(u) : "f"(x));
  return u;
}

__device__ __forceinline__ void ldsm4(uint32_t addr, uint32_t& r0, uint32_t& r1,
                                      uint32_t& r2, uint32_t& r3) {
  asm volatile("ldmatrix.sync.aligned.m8n8.x4.shared.b16 {%0,%1,%2,%3}, [%4];"
               : "=r"(r0), "=r"(r1), "=r"(r2), "=r"(r3) : "r"(addr));
}

__device__ __forceinline__ void mma_tf32(float* c, const uint32_t* a, uint32_t b0, uint32_t b1) {
  asm volatile(
      "mma.sync.aligned.m16n8k8.row.col.f32.tf32.tf32.f32 "
      "{%0,%1,%2,%3}, {%4,%5,%6,%7}, {%8,%9}, {%0,%1,%2,%3};"
      : "+f"(c[0]), "+f"(c[1]), "+f"(c[2]), "+f"(c[3])
      : "r"(a[0]), "r"(a[1]), "r"(a[2]), "r"(a[3]), "r"(b0), "r"(b1));
}

__global__ void __launch_bounds__(128) fa_tf32_kernel(
    const float* __restrict__ Q, const float* __restrict__ K,
    const float* __restrict__ V, float* __restrict__ Out) {
  extern __shared__ float smem[];
  float* Qs = smem;                      // [64][132]
  float* Ks = smem + BM * SSTRIDE;       // [64][132]
  float* Vs = smem + 2 * BM * SSTRIDE;   // [64][136]  row-major (k, d)

  const int tid  = threadIdx.x;
  const int warp = tid >> 5;
  const int lane = tid & 31;
  const int bh   = blockIdx.y;
  const int qt   = (int)gridDim.x - 1 - (int)blockIdx.x;  // heavy tiles first

  const size_t base = (size_t)bh * T_SEQ * D_HEAD;
  const float* qg  = Q + base + (size_t)qt * BM * D_HEAD;
  const float* kgb = K + base;
  const float* vgb = V + base;

  // ---- Load Q tile (fp32 -> tf32 rna) ----
  #pragma unroll
  for (int i = 0; i < 16; ++i) {
    int idx = tid + i * 128;
    int r = idx >> 5, c = (idx & 31) << 2;
    float4 x = *reinterpret_cast<const float4*>(qg + r * D_HEAD + c);
    uint32_t* d = reinterpret_cast<uint32_t*>(Qs + r * SSTRIDE + c);
    d[0] = f2tf32(x.x); d[1] = f2tf32(x.y); d[2] = f2tf32(x.z); d[3] = f2tf32(x.w);
  }
  __syncthreads();

  // ---- Preload Q A-fragments (m16k8 x 16 kblocks) via ldmatrix.x4 ----
  uint32_t QA[16][4];
  {
    int row = warp * 16 + (lane & 7) + ((lane >> 3) & 1) * 8;
    int col = ((lane >> 4) << 2);
    const float* p = Qs + row * SSTRIDE + col;
    #pragma unroll
    for (int kb = 0; kb < 16; ++kb) {
      uint32_t a = (uint32_t)__cvta_generic_to_shared(p + kb * 8);
      ldsm4(a, QA[kb][0], QA[kb][1], QA[kb][2], QA[kb][3]);
    }
  }

  float Oacc[16][4];
  #pragma unroll
  for (int dt = 0; dt < 16; ++dt) {
    Oacc[dt][0] = 0.f; Oacc[dt][1] = 0.f; Oacc[dt][2] = 0.f; Oacc[dt][3] = 0.f;
  }
  float m0 = -1e30f, m1 = -1e30f, l0 = 0.f, l1 = 0.f;

  const float sl2e = 1.4426950408889634f * 0.08838834764831845f;  // log2(e)/sqrt(128)

  const int num_kt = qt + 1;
  for (int kt = 0; kt < num_kt; ++kt) {
    __syncthreads();  // previous tile's consumers done before overwrite
    const float* kg = kgb + (size_t)kt * BN * D_HEAD;
    const float* vg = vgb + (size_t)kt * BN * D_HEAD;
    #pragma unroll
    for (int i = 0; i < 16; ++i) {
      int idx = tid + i * 128;
      int r = idx >> 5, c = (idx & 31) << 2;
      float4 xk = *reinterpret_cast<const float4*>(kg + r * D_HEAD + c);
      uint32_t* dk = reinterpret_cast<uint32_t*>(Ks + r * SSTRIDE + c);
      dk[0] = f2tf32(xk.x); dk[1] = f2tf32(xk.y); dk[2] = f2tf32(xk.z); dk[3] = f2tf32(xk.w);
      float4 xv = *reinterpret_cast<const float4*>(vg + r * D_HEAD + c);
      uint32_t* dv = reinterpret_cast<uint32_t*>(Vs + r * VSTRIDE + c);
      dv[0] = f2tf32(xv.x); dv[1] = f2tf32(xv.y); dv[2] = f2tf32(xv.z); dv[3] = f2tf32(xv.w);
    }
    __syncthreads();

    // ---- GEMM1: S[16 x 64] = Q . K^T ----
    float S[8][4];
    #pragma unroll
    for (int nt = 0; nt < 8; ++nt) { S[nt][0]=0.f; S[nt][1]=0.f; S[nt][2]=0.f; S[nt][3]=0.f; }
    {
      int brow = lane & 7;
      int bcol = (lane >> 3) << 2;
      #pragma unroll
      for (int nt = 0; nt < 8; ++nt) {
        const float* kb8 = Ks + (nt * 8 + brow) * SSTRIDE + bcol;
        #pragma unroll
        for (int kbp = 0; kbp < 8; ++kbp) {
          uint32_t b0, b1, b2, b3;
          ldsm4((uint32_t)__cvta_generic_to_shared(kb8 + kbp * 16), b0, b1, b2, b3);
          mma_tf32(S[nt], QA[2 * kbp],     b0, b1);
          mma_tf32(S[nt], QA[2 * kbp + 1], b2, b3);
        }
      }
    }

    // ---- causal mask (diagonal tile only) ----
    if (kt == qt) {
      int rloc = warp * 16 + (lane >> 2);
      #pragma unroll
      for (int nt = 0; nt < 8; ++nt) {
        int cloc = nt * 8 + ((lane & 3) << 1);
        if (cloc     > rloc    ) S[nt][0] = -1e30f;
        if (cloc + 1 > rloc    ) S[nt][1] = -1e30f;
        if (cloc     > rloc + 8) S[nt][2] = -1e30f;
        if (cloc + 1 > rloc + 8) S[nt][3] = -1e30f;
      }
    }

    // ---- online softmax ----
    float rm0 = -1e30f, rm1 = -1e30f;
    #pragma unroll
    for (int nt = 0; nt < 8; ++nt) {
      rm0 = fmaxf(rm0, fmaxf(S[nt][0], S[nt][1]));
      rm1 = fmaxf(rm1, fmaxf(S[nt][2], S[nt][3]));
    }
    rm0 = fmaxf(rm0, __shfl_xor_sync(0xffffffffu, rm0, 1));
    rm0 = fmaxf(rm0, __shfl_xor_sync(0xffffffffu, rm0, 2));
    rm1 = fmaxf(rm1, __shfl_xor_sync(0xffffffffu, rm1, 1));
    rm1 = fmaxf(rm1, __shfl_xor_sync(0xffffffffu, rm1, 2));

    float nm0 = fmaxf(m0, rm0), nm1 = fmaxf(m1, rm1);
    float al0 = exp2f((m0 - nm0) * sl2e);
    float al1 = exp2f((m1 - nm1) * sl2e);
    m0 = nm0; m1 = nm1;

    float ps0 = 0.f, ps1 = 0.f;
    #pragma unroll
    for (int nt = 0; nt < 8; ++nt) {
      S[nt][0] = exp2f((S[nt][0] - m0) * sl2e);
      S[nt][1] = exp2f((S[nt][1] - m0) * sl2e);
      S[nt][2] = exp2f((S[nt][2] - m1) * sl2e);
      S[nt][3] = exp2f((S[nt][3] - m1) * sl2e);
      ps0 += S[nt][0] + S[nt][1];
      ps1 += S[nt][2] + S[nt][3];
    }
    l0 = l0 * al0 + ps0;
    l1 = l1 * al1 + ps1;

    #pragma unroll
    for (int dt = 0; dt < 16; ++dt) {
      Oacc[dt][0] *= al0; Oacc[dt][1] *= al0;
      Oacc[dt][2] *= al1; Oacc[dt][3] *= al1;
    }

    // ---- C-layout -> A-layout for P (tf32 convert + quad shuffles) ----
    uint32_t PA[8][4];
    {
      int t = lane & 3;
      int src_lo = (lane & ~3) | (t >> 1);
      int src_hi = src_lo + 2;
      bool odd = (t & 1) != 0;
      #pragma unroll
      for (int nt = 0; nt < 8; ++nt) {
        uint32_t p0 = f2tf32(S[nt][0]);
        uint32_t p1 = f2tf32(S[nt][1]);
        uint32_t p2 = f2tf32(S[nt][2]);
        uint32_t p3 = f2tf32(S[nt][3]);
        uint32_t x0 = __shfl_sync(0xffffffffu, p0, src_lo);
        uint32_t x1 = __shfl_sync(0xffffffffu, p1, src_lo);
        PA[nt][0] = odd ? x1 : x0;
        uint32_t y0 = __shfl_sync(0xffffffffu, p2, src_lo);
        uint32_t y1 = __shfl_sync(0xffffffffu, p3, src_lo);
        PA[nt][1] = odd ? y1 : y0;
        x0 = __shfl_sync(0xffffffffu, p0, src_hi);
        x1 = __shfl_sync(0xffffffffu, p1, src_hi);
        PA[nt][2] = odd ? x1 : x0;
        y0 = __shfl_sync(0xffffffffu, p2, src_hi);
        y1 = __shfl_sync(0xffffffffu, p3, src_hi);
        PA[nt][3] = odd ? y1 : y0;
      }
    }

    // ---- GEMM2: O += P . V  (conflict-free scalar B-fragment loads, stride 136) ----
    {
      int t = lane & 3, g = lane >> 2;
      #pragma unroll
      for (int dt = 0; dt < 16; ++dt) {
        #pragma unroll
        for (int kb = 0; kb < 8; ++kb) {
          uint32_t b0 = *reinterpret_cast<const uint32_t*>(Vs + (kb * 8 + t)     * VSTRIDE + dt * 8 + g);
          uint32_t b1 = *reinterpret_cast<const uint32_t*>(Vs + (kb * 8 + t + 4) * VSTRIDE + dt * 8 + g);
          mma_tf32(Oacc[dt], PA[kb], b0, b1);
        }
      }
    }
  }

  // ---- epilogue: normalize and store ----
  l0 += __shfl_xor_sync(0xffffffffu, l0, 1);
  l0 += __shfl_xor_sync(0xffffffffu, l0, 2);
  l1 += __shfl_xor_sync(0xffffffffu, l1, 1);
  l1 += __shfl_xor_sync(0xffffffffu, l1, 2);
  float inv0 = 1.f / l0, inv1 = 1.f / l1;

  int gr0 = qt * BM + warp * 16 + (lane >> 2);
  float* og = Out + base;
  int cbase = (lane & 3) << 1;
  #pragma unroll
  for (int dt = 0; dt < 16; ++dt) {
    float2 v0 = make_float2(Oacc[dt][0] * inv0, Oacc[dt][1] * inv0);
    float2 v1 = make_float2(Oacc[dt][2] * inv1, Oacc[dt][3] * inv1);
    *reinterpret_cast<float2*>(og + (size_t)gr0       * D_HEAD + dt * 8 + cbase) = v0;
    *reinterpret_cast<float2*>(og + (size_t)(gr0 + 8) * D_HEAD + dt * 8 + cbase) = v1;
  }
}

}  // namespace

extern "C" void kernel_launch(void* const* d_in, const int* in_sizes, int n_in,
                              void* d_out, int out_size) {
  const float* q = (const float*)d_in[0];
  const float* k = (const float*)d_in[1];
  const float* v = (const float*)d_in[2];
  float* o = (float*)d_out;

  int bh = in_sizes[0] / (T_SEQ * D_HEAD);  // B*H = 32

  cudaFuncSetAttribute(fa_tf32_kernel, cudaFuncAttributeMaxDynamicSharedMemorySize, SMEM_BYTES);
  dim3 grid(T_SEQ / BM, bh);
  fa_tf32_kernel<<<grid, 128, SMEM_BYTES>>>(q, k, v, o);
}

// round 5
// speedup vs baseline: 1.8360x; 1.8360x over previous
#include <cuda_runtime.h>
#include <cstdint>

namespace {

constexpr int T_SEQ  = 4096;
constexpr int D_HEAD = 128;
constexpr int BM = 128;             // q rows per CTA (8 warps x 16 rows)
constexpr int BN = 64;              // kv rows per tile
constexpr int SSTRIDE = 132;        // Q/K row stride (floats)
constexpr int VSTRIDE = 136;        // V row stride (floats) - conflict-free GEMM2 frags
constexpr int QS_FLOATS = BM * SSTRIDE;    // 16896
constexpr int KS_FLOATS = BN * SSTRIDE;    // 8448
constexpr int VS_FLOATS = BN * VSTRIDE;    // 8704
constexpr int SMEM_BYTES = (QS_FLOATS + 2 * KS_FLOATS + 2 * VS_FLOATS) * 4;  // 204800

__device__ __forceinline__ uint32_t f2tf32(float x) {
  uint32_t u;
  asm("cvt.rna.tf32.f32 %0, %1;" : "=r"(u) : "f"(x));
  return u;
}

__device__ __forceinline__ void ldsm4(uint32_t addr, uint32_t& r0, uint32_t& r1,
                                      uint32_t& r2, uint32_t& r3) {
  asm volatile("ldmatrix.sync.aligned.m8n8.x4.shared.b16 {%0,%1,%2,%3}, [%4];"
               : "=r"(r0), "=r"(r1), "=r"(r2), "=r"(r3) : "r"(addr));
}

__device__ __forceinline__ void mma_tf32(float* c, uint32_t a0, uint32_t a1,
                                         uint32_t a2, uint32_t a3,
                                         uint32_t b0, uint32_t b1) {
  asm volatile(
      "mma.sync.aligned.m16n8k8.row.col.f32.tf32.tf32.f32 "
      "{%0,%1,%2,%3}, {%4,%5,%6,%7}, {%8,%9}, {%0,%1,%2,%3};"
      : "+f"(c[0]), "+f"(c[1]), "+f"(c[2]), "+f"(c[3])
      : "r"(a0), "r"(a1), "r"(a2), "r"(a3), "r"(b0), "r"(b1));
}

__device__ __forceinline__ void cpasync16(uint32_t dst, const void* src) {
  asm volatile("cp.async.cg.shared.global [%0], [%1], 16;" :: "r"(dst), "l"(src));
}
__device__ __forceinline__ void cp_commit() {
  asm volatile("cp.async.commit_group;");
}

__global__ void __launch_bounds__(256, 1) fa_tf32_kernel(
    const float* __restrict__ Q, const float* __restrict__ K,
    const float* __restrict__ V, float* __restrict__ Out) {
  extern __shared__ float smem[];
  float* Qs = smem;                               // [128][132] raw fp32
  float* Ks0 = smem + QS_FLOATS;                  // [64][132] raw, rows sigma-permuted
  float* Ks1 = Ks0 + KS_FLOATS;
  float* Vs0 = Ks1 + KS_FLOATS;                   // [64][136] raw
  float* Vs1 = Vs0 + VS_FLOATS;

  const int tid  = threadIdx.x;
  const int warp = tid >> 5;
  const int lane = tid & 31;
  const int bh   = blockIdx.y;
  const int qt   = (int)gridDim.x - 1 - (int)blockIdx.x;  // heavy tiles first

  const size_t base = (size_t)bh * T_SEQ * D_HEAD;
  const float* qg  = Q + base + (size_t)qt * BM * D_HEAD;
  const float* kgb = K + base;
  const float* vgb = V + base;

  const uint32_t qs_b  = (uint32_t)__cvta_generic_to_shared(Qs);
  const uint32_t ks_b[2] = {(uint32_t)__cvta_generic_to_shared(Ks0),
                            (uint32_t)__cvta_generic_to_shared(Ks1)};
  const uint32_t vs_b[2] = {(uint32_t)__cvta_generic_to_shared(Vs0),
                            (uint32_t)__cvta_generic_to_shared(Vs1)};

  // ---- Q tile via cp.async (raw fp32), group 0 ----
  #pragma unroll
  for (int i = 0; i < 16; ++i) {
    int g = i * 256 + tid;           // 4096 16B-chunks: 128 rows x 32 chunks
    int r = g >> 5, ch = g & 31;
    cpasync16(qs_b + (uint32_t)(r * SSTRIDE + ch * 4) * 4u, qg + r * D_HEAD + ch * 4);
  }
  cp_commit();

  // tile loader: K rows permuted by 3-bit left-rotate within each 8-group
  auto load_tile = [&](int kt, int buf) {
    const float* kg = kgb + (size_t)kt * BN * D_HEAD;
    const float* vg = vgb + (size_t)kt * BN * D_HEAD;
    #pragma unroll
    for (int i = 0; i < 8; ++i) {
      int g = i * 256 + tid;         // 2048 chunks: 64 rows x 32
      int r = g >> 5, ch = g & 31;
      int r3 = r & 7;
      int pr = (r & ~7) | (((r3 << 1) | (r3 >> 2)) & 7);
      cpasync16(ks_b[buf] + (uint32_t)(pr * SSTRIDE + ch * 4) * 4u, kg + r * D_HEAD + ch * 4);
    }
    #pragma unroll
    for (int i = 0; i < 8; ++i) {
      int g = i * 256 + tid;
      int r = g >> 5, ch = g & 31;
      cpasync16(vs_b[buf] + (uint32_t)(r * VSTRIDE + ch * 4) * 4u, vg + r * D_HEAD + ch * 4);
    }
    cp_commit();
  };

  const int num_kt = 2 * qt + 2;
  load_tile(0, 0);                                  // group 1

  // wait for Q (<=1 pending), build Q A-fragments (cvt.rna once)
  asm volatile("cp.async.wait_group 1;" ::: "memory");
  __syncthreads();

  uint32_t QA[16][4];
  {
    int row = warp * 16 + (lane & 7) + ((lane >> 3) & 1) * 8;
    int col = ((lane >> 4) << 2);
    const float* p = Qs + row * SSTRIDE + col;
    #pragma unroll
    for (int kb = 0; kb < 16; ++kb) {
      uint32_t a = (uint32_t)__cvta_generic_to_shared(p + kb * 8);
      ldsm4(a, QA[kb][0], QA[kb][1], QA[kb][2], QA[kb][3]);
      QA[kb][0] = f2tf32(__uint_as_float(QA[kb][0]));
      QA[kb][1] = f2tf32(__uint_as_float(QA[kb][1]));
      QA[kb][2] = f2tf32(__uint_as_float(QA[kb][2]));
      QA[kb][3] = f2tf32(__uint_as_float(QA[kb][3]));
    }
  }

  float Oacc[16][4];
  #pragma unroll
  for (int dt = 0; dt < 16; ++dt) {
    Oacc[dt][0] = 0.f; Oacc[dt][1] = 0.f; Oacc[dt][2] = 0.f; Oacc[dt][3] = 0.f;
  }
  float m0 = -1e30f, m1 = -1e30f, l0 = 0.f, l1 = 0.f;

  const float sl2e = 1.4426950408889634f * 0.08838834764831845f;  // log2(e)/sqrt(128)
  const int grow0 = qt * BM + warp * 16;            // this warp's first q row

  for (int kt = 0; kt < num_kt; ++kt) {
    if (kt + 1 < num_kt) {
      load_tile(kt + 1, (kt + 1) & 1);
      asm volatile("cp.async.wait_group 1;" ::: "memory");
    } else {
      asm volatile("cp.async.wait_group 0;" ::: "memory");
    }
    __syncthreads();

    const int ktbase = kt * BN;
    const bool active = (ktbase <= grow0 + 15);
    if (active) {
      const float* Ks = (kt & 1) ? Ks1 : Ks0;
      const float* Vs = (kt & 1) ? Vs1 : Vs0;

      // ---- GEMM1: S[16 x 64] = Q . K^T  (K raw fp32 -> HW tf32 truncation) ----
      float S[8][4];
      #pragma unroll
      for (int nt = 0; nt < 8; ++nt) { S[nt][0]=0.f; S[nt][1]=0.f; S[nt][2]=0.f; S[nt][3]=0.f; }
      {
        int brow = lane & 7;
        int bcol = (lane >> 3) << 2;
        #pragma unroll
        for (int nt = 0; nt < 8; ++nt) {
          const float* kb8 = Ks + (nt * 8 + brow) * SSTRIDE + bcol;
          #pragma unroll
          for (int kbp = 0; kbp < 8; ++kbp) {
            uint32_t b0, b1, b2, b3;
            ldsm4((uint32_t)__cvta_generic_to_shared(kb8 + kbp * 16), b0, b1, b2, b3);
            mma_tf32(S[nt], QA[2*kbp][0],   QA[2*kbp][1],   QA[2*kbp][2],   QA[2*kbp][3],   b0, b1);
            mma_tf32(S[nt], QA[2*kbp+1][0], QA[2*kbp+1][1], QA[2*kbp+1][2], QA[2*kbp+1][3], b2, b3);
          }
        }
      }

      // ---- causal mask (sigma-permuted cols: c0/c2 -> k=t, c1/c3 -> k=t+4) ----
      if (ktbase + BN - 1 > grow0) {
        int grow = grow0 + (lane >> 2);
        int gc   = ktbase + (lane & 3);
        #pragma unroll
        for (int nt = 0; nt < 8; ++nt) {
          int c0 = gc + nt * 8;
          int c1 = c0 + 4;
          if (c0 > grow)     S[nt][0] = -1e30f;
          if (c1 > grow)     S[nt][1] = -1e30f;
          if (c0 > grow + 8) S[nt][2] = -1e30f;
          if (c1 > grow + 8) S[nt][3] = -1e30f;
        }
      }

      // ---- online softmax ----
      float rm0 = -1e30f, rm1 = -1e30f;
      #pragma unroll
      for (int nt = 0; nt < 8; ++nt) {
        rm0 = fmaxf(rm0, fmaxf(S[nt][0], S[nt][1]));
        rm1 = fmaxf(rm1, fmaxf(S[nt][2], S[nt][3]));
      }
      rm0 = fmaxf(rm0, __shfl_xor_sync(0xffffffffu, rm0, 1));
      rm0 = fmaxf(rm0, __shfl_xor_sync(0xffffffffu, rm0, 2));
      rm1 = fmaxf(rm1, __shfl_xor_sync(0xffffffffu, rm1, 1));
      rm1 = fmaxf(rm1, __shfl_xor_sync(0xffffffffu, rm1, 2));

      float nm0 = fmaxf(m0, rm0), nm1 = fmaxf(m1, rm1);
      float al0 = exp2f((m0 - nm0) * sl2e);
      float al1 = exp2f((m1 - nm1) * sl2e);
      m0 = nm0; m1 = nm1;

      float ps0 = 0.f, ps1 = 0.f;
      #pragma unroll
      for (int nt = 0; nt < 8; ++nt) {
        S[nt][0] = exp2f((S[nt][0] - m0) * sl2e);
        S[nt][1] = exp2f((S[nt][1] - m0) * sl2e);
        S[nt][2] = exp2f((S[nt][2] - m1) * sl2e);
        S[nt][3] = exp2f((S[nt][3] - m1) * sl2e);
        ps0 += S[nt][0] + S[nt][1];
        ps1 += S[nt][2] + S[nt][3];
      }
      l0 = l0 * al0 + ps0;
      l1 = l1 * al1 + ps1;

      #pragma unroll
      for (int dt = 0; dt < 16; ++dt) {
        Oacc[dt][0] *= al0; Oacc[dt][1] *= al0;
        Oacc[dt][2] *= al1; Oacc[dt][3] *= al1;
      }

      // ---- P -> tf32 A-fragments (register relabel, zero shuffles) ----
      uint32_t PAu[8][4];
      #pragma unroll
      for (int nt = 0; nt < 8; ++nt) {
        PAu[nt][0] = f2tf32(S[nt][0]);   // a0 = P[g][t]
        PAu[nt][1] = f2tf32(S[nt][2]);   // a1 = P[g+8][t]
        PAu[nt][2] = f2tf32(S[nt][1]);   // a2 = P[g][t+4]
        PAu[nt][3] = f2tf32(S[nt][3]);   // a3 = P[g+8][t+4]
      }

      // ---- GEMM2: O += P . V  (V raw fp32, conflict-free stride-136 frags) ----
      {
        int t = lane & 3, g = lane >> 2;
        #pragma unroll
        for (int dt = 0; dt < 16; ++dt) {
          #pragma unroll
          for (int kb = 0; kb < 8; ++kb) {
            uint32_t b0 = *reinterpret_cast<const uint32_t*>(Vs + (kb * 8 + t)     * VSTRIDE + dt * 8 + g);
            uint32_t b1 = *reinterpret_cast<const uint32_t*>(Vs + (kb * 8 + t + 4) * VSTRIDE + dt * 8 + g);
            mma_tf32(Oacc[dt], PAu[kb][0], PAu[kb][1], PAu[kb][2], PAu[kb][3], b0, b1);
          }
        }
      }
    }
    __syncthreads();   // compute done before next prefetch overwrites this buffer
  }

  // ---- epilogue: normalize and store ----
  l0 += __shfl_xor_sync(0xffffffffu, l0, 1);
  l0 += __shfl_xor_sync(0xffffffffu, l0, 2);
  l1 += __shfl_xor_sync(0xffffffffu, l1, 1);
  l1 += __shfl_xor_sync(0xffffffffu, l1, 2);
  float inv0 = 1.f / l0, inv1 = 1.f / l1;

  int gr0 = grow0 + (lane >> 2);
  float* og = Out + base;
  int cbase = (lane & 3) << 1;
  #pragma unroll
  for (int dt = 0; dt < 16; ++dt) {
    float2 v0 = make_float2(Oacc[dt][0] * inv0, Oacc[dt][1] * inv0);
    float2 v1 = make_float2(Oacc[dt][2] * inv1, Oacc[dt][3] * inv1);
    *reinterpret_cast<float2*>(og + (size_t)gr0       * D_HEAD + dt * 8 + cbase) = v0;
    *reinterpret_cast<float2*>(og + (size_t)(gr0 + 8) * D_HEAD + dt * 8 + cbase) = v1;
  }
}

}  // namespace

extern "C" void kernel_launch(void* const* d_in, const int* in_sizes, int n_in,
                              void* d_out, int out_size) {
  const float* q = (const float*)d_in[0];
  const float* k = (const float*)d_in[1];
  const float* v = (const float*)d_in[2];
  float* o = (float*)d_out;

  int bh = in_sizes[0] / (T_SEQ * D_HEAD);  // B*H = 32

  cudaFuncSetAttribute(fa_tf32_kernel, cudaFuncAttributeMaxDynamicSharedMemorySize, SMEM_BYTES);
  dim3 grid(T_SEQ / BM, bh);
  fa_tf32_kernel<<<grid, 256, SMEM_BYTES>>>(q, k, v, o);
}